// round 5
// baseline (speedup 1.0000x reference)
#include <cuda_runtime.h>
#include <cuda_fp16.h>
#include <cstdint>

// Problem constants (fixed shapes per reference)
#define NV 100000      // vertices
#define TT 128         // temporal depth
#define EE 1600000     // edges
#define KK 9           // conv kernel
#define LL 3           // layers

// ---------------- scratch (device globals; no runtime allocation) -----------
__device__ __half g_hA[(size_t)NV * TT];   // ping  (fp16 activations)
__device__ __half g_hB[(size_t)NV * TT];   // pong
__device__ __half g_xh[(size_t)NV * TT];   // final activation (fp16, flat)
__device__ int    g_deg[NV];
__device__ int    g_fill[NV];              // fill cursor, seeded = rowptr
__device__ int    g_rowptr[NV + 1];
__device__ int    g_col[EE];

// ---------------- CSR build --------------------------------------------------
// zero degree counters AND initialize y with the output bias (independent work)
__global__ void zero_init_kernel(const float* __restrict__ bout,
                                 float* __restrict__ y) {
    int i = blockIdx.x * blockDim.x + threadIdx.x;
    if (i < NV) g_deg[i] = 0;
    if (i < TT * 3) y[i] = __ldg(&bout[i % 3]);
}

__global__ void hist_kernel(const int* __restrict__ dst) {
    int e = blockIdx.x * blockDim.x + threadIdx.x;
    if (e < EE) atomicAdd(&g_deg[dst[e]], 1);
}

// Single-block exclusive scan of g_deg -> g_rowptr (and seed g_fill = rowptr).
#define SB_T 1024
#define SB_CH ((NV + SB_T - 1) / SB_T)   // 98
__global__ void scan_kernel() {
    __shared__ int s[SB_T];
    int t = threadIdx.x;
    int lo = t * SB_CH;
    int hi = lo + SB_CH; if (hi > NV) hi = NV;
    int sum = 0;
    for (int i = lo; i < hi; i++) sum += g_deg[i];
    s[t] = sum;
    __syncthreads();
    // Hillis-Steele inclusive scan over 1024
    for (int off = 1; off < SB_T; off <<= 1) {
        int v = (t >= off) ? s[t - off] : 0;
        __syncthreads();
        s[t] += v;
        __syncthreads();
    }
    int run = s[t] - sum;   // exclusive prefix of this thread's chunk
    for (int i = lo; i < hi; i++) {
        g_rowptr[i] = run;
        g_fill[i]   = run;
        run += g_deg[i];
    }
    if (t == SB_T - 1) g_rowptr[NV] = run;
}

__global__ void fill_kernel(const int* __restrict__ src,
                            const int* __restrict__ dst) {
    int e = blockIdx.x * blockDim.x + threadIdx.x;
    if (e < EE) {
        int pos = atomicAdd(&g_fill[dst[e]], 1);
        g_col[pos] = src[e];
    }
}

// ---------------- fp16 helpers ------------------------------------------------
__device__ __forceinline__ void acc_u4(float* a, uint4 u) {
    __half2* p = reinterpret_cast<__half2*>(&u);
#pragma unroll
    for (int i = 0; i < 4; i++) {
        float2 f = __half22float2(p[i]);
        a[2 * i]     += f.x;
        a[2 * i + 1] += f.y;
    }
}

__device__ __forceinline__ uint4 f8_to_u4(const float* o) {
    uint4 u;
    __half2 h0 = __float22half2_rn(make_float2(o[0], o[1]));
    __half2 h1 = __float22half2_rn(make_float2(o[2], o[3]));
    __half2 h2 = __float22half2_rn(make_float2(o[4], o[5]));
    __half2 h3 = __float22half2_rn(make_float2(o[6], o[7]));
    u.x = *reinterpret_cast<unsigned*>(&h0);
    u.y = *reinterpret_cast<unsigned*>(&h1);
    u.z = *reinterpret_cast<unsigned*>(&h2);
    u.w = *reinterpret_cast<unsigned*>(&h3);
    return u;
}

// ---------------- layer-0 conv (fp32 in -> fp16 out) --------------------------
__global__ void conv_kernel(const float* __restrict__ x,
                            const float* __restrict__ w,
                            const float* __restrict__ b,
                            __half* __restrict__ hout) {
    __shared__ float s[2][TT + 8];
    int ln = threadIdx.x >> 7;
    int t  = threadIdx.x & 127;
    int n  = blockIdx.x * 2 + ln;
    s[ln][t + 4] = x[(size_t)n * TT + t];
    if (t < 4) { s[ln][t] = 0.0f; s[ln][t + TT + 4] = 0.0f; }
    __syncthreads();
    float wv[KK];
#pragma unroll
    for (int k = 0; k < KK; k++) wv[k] = __ldg(&w[k]);
    float acc = __ldg(&b[0]);
#pragma unroll
    for (int k = 0; k < KK; k++) acc += wv[k] * s[ln][t + k];
    hout[(size_t)n * TT + t] = __float2half_rn(acc);
}

// ---------------- gather: warp = 1 node, half-warp = 1 edge -------------------
// Lane layout: half = lane>>4 (edge slot), hl = lane&15 (16B chunk of row).
// Row = 128 fp16 = 256B = 16 x uint4. acc[8] = cols [8*hl, 8*hl+8).
// After combine, lanes 0..15 hold relu(mean) of the node's row.
__device__ __forceinline__ void gather_mean_relu16(int node, int lane,
                                                   const uint4* __restrict__ h,
                                                   float* acc, int* cnt_out) {
    int half = lane >> 4;
    int hl   = lane & 15;
#pragma unroll
    for (int q = 0; q < 8; q++) acc[q] = 0.f;
    int beg = g_rowptr[node];
    int end = g_rowptr[node + 1];
    int cnt = end - beg;
    *cnt_out = cnt;
    // self loop (slot 0 only; predicated load, no duplicate traffic)
    if (half == 0) {
        uint4 sv = __ldg(&h[(size_t)node * 16 + hl]);
        acc_u4(acc, sv);
    }
    // neighbors in chunks of 32 indices held in lane registers
    for (int c0 = 0; c0 < cnt; c0 += 32) {
        int rem = cnt - c0; if (rem > 32) rem = 32;
        int myc = (lane < rem) ? __ldg(&g_col[beg + c0 + lane]) : 0;
#pragma unroll 4
        for (int p = 0; p < rem; p += 2) {
            int jj = p + half;
            int srcn = __shfl_sync(0xffffffffu, myc, jj);
            if (jj < rem) {
                uint4 v = __ldg(&h[(size_t)srcn * 16 + hl]);
                acc_u4(acc, v);
            }
        }
    }
    // combine the two edge slots
#pragma unroll
    for (int q = 0; q < 8; q++)
        acc[q] += __shfl_down_sync(0xffffffffu, acc[q], 16);
    float inv = 1.0f / (float)(cnt + 1);
#pragma unroll
    for (int q = 0; q < 8; q++)
        acc[q] = fmaxf(acc[q] * inv, 0.0f);   // valid in lanes 0..15
}

// ---------------- fused agg(+relu) + next-layer conv -------------------------
__global__ void agg_conv_kernel(const uint4* __restrict__ hin,
                                uint4* __restrict__ hout,
                                const float* __restrict__ w,
                                const float* __restrict__ b) {
    int warp = (blockIdx.x * blockDim.x + threadIdx.x) >> 5;
    int lane = threadIdx.x & 31;
    if (warp >= NV) return;
    float acc[8]; int cnt;
    gather_mean_relu16(warp, lane, hin, acc, &cnt);

    int hl = lane & 15;
    const unsigned m = 0xffffffffu;
    // halo: prev lane's last 4, next lane's first 4 (within lanes 0..15)
    float v[16];
#pragma unroll
    for (int j = 0; j < 4; j++) {
        float pv = __shfl_up_sync(m, acc[4 + j], 1);
        v[j] = (hl == 0) ? 0.f : pv;
    }
#pragma unroll
    for (int q = 0; q < 8; q++) v[4 + q] = acc[q];
#pragma unroll
    for (int j = 0; j < 4; j++) {
        float nx = __shfl_down_sync(m, acc[j], 1);
        v[12 + j] = (hl == 15) ? 0.f : nx;
    }
    float wv[KK];
#pragma unroll
    for (int k = 0; k < KK; k++) wv[k] = __ldg(&w[k]);
    float bv = __ldg(&b[0]);
    float o[8];
#pragma unroll
    for (int q = 0; q < 8; q++) {
        float s = bv;
#pragma unroll
        for (int k = 0; k < KK; k++) s += wv[k] * v[q + k];
        o[q] = s;
    }
    if (lane < 16)
        hout[(size_t)warp * 16 + hl] = f8_to_u4(o);
}

// Final aggregation: relu(mean) only, into g_xh (fp16, flat for projection).
__global__ void agg_final_kernel(const uint4* __restrict__ hin) {
    int warp = (blockIdx.x * blockDim.x + threadIdx.x) >> 5;
    int lane = threadIdx.x & 31;
    if (warp >= NV) return;
    float acc[8]; int cnt;
    gather_mean_relu16(warp, lane, hin, acc, &cnt);
    if (lane < 16)
        reinterpret_cast<uint4*>(g_xh)[(size_t)warp * 16 + (lane & 15)] = f8_to_u4(acc);
}

// ---------------- output projection ------------------------------------------
// Blocks tile the N dimension (chunk = 256); W chunk in registers; warps
// stride over the 128 output rows; x read as fp16. y pre-initialized with bias.
#define OCHUNK 256
__global__ void out_kernel2(const float* __restrict__ Wout, float* __restrict__ y) {
    int n0 = blockIdx.x * OCHUNK;
    int C  = NV - n0; if (C > OCHUNK) C = OCHUNK;   // multiple of 8 (NV=100000)
    int w  = threadIdx.x >> 5;
    int lane = threadIdx.x & 31;

    float w0[8], w1[8], w2[8];
#pragma unroll
    for (int q = 0; q < 8; q++) {
        int idx = lane * 8 + q;
        bool val = idx < C;
        int n = n0 + idx;
        w0[q] = val ? __ldg(&Wout[0 * NV + n]) : 0.f;
        w1[q] = val ? __ldg(&Wout[1 * NV + n]) : 0.f;
        w2[q] = val ? __ldg(&Wout[2 * NV + n]) : 0.f;
    }

    for (int a = w; a < TT; a += 8) {
        const __half* xr = g_xh + (size_t)a * NV + n0;
        float p0 = 0.f, p1 = 0.f, p2 = 0.f;
#pragma unroll
        for (int q4 = 0; q4 < 2; q4++) {
            int idx = lane * 8 + q4 * 4;
            if (idx < C) {
                uint2 u = *reinterpret_cast<const uint2*>(xr + idx);
                __half2 h0 = *reinterpret_cast<__half2*>(&u.x);
                __half2 h1 = *reinterpret_cast<__half2*>(&u.y);
                float2 f0 = __half22float2(h0);
                float2 f1 = __half22float2(h1);
                int q = q4 * 4;
                p0 += f0.x * w0[q] + f0.y * w0[q + 1] + f1.x * w0[q + 2] + f1.y * w0[q + 3];
                p1 += f0.x * w1[q] + f0.y * w1[q + 1] + f1.x * w1[q + 2] + f1.y * w1[q + 3];
                p2 += f0.x * w2[q] + f0.y * w2[q + 1] + f1.x * w2[q + 2] + f1.y * w2[q + 3];
            }
        }
#pragma unroll
        for (int off = 16; off > 0; off >>= 1) {
            p0 += __shfl_down_sync(0xffffffffu, p0, off);
            p1 += __shfl_down_sync(0xffffffffu, p1, off);
            p2 += __shfl_down_sync(0xffffffffu, p2, off);
        }
        if (lane == 0) {
            atomicAdd(&y[a * 3 + 0], p0);
            atomicAdd(&y[a * 3 + 1], p1);
            atomicAdd(&y[a * 3 + 2], p2);
        }
    }
}

// ---------------- launch -----------------------------------------------------
extern "C" void kernel_launch(void* const* d_in, const int* in_sizes, int n_in,
                              void* d_out, int out_size) {
    const float* x_in    = (const float*)d_in[0];
    const int*   ei      = (const int*)d_in[1];
    const float* conv_w  = (const float*)d_in[2];   // [L,1,1,K]
    const float* conv_b  = (const float*)d_in[3];   // [L,1]
    const float* W_out   = (const float*)d_in[4];   // [3, N]
    const float* b_out   = (const float*)d_in[5];   // [3]
    float* y = (float*)d_out;                       // [T, 3]

    const int* src = ei;
    const int* dst = ei + EE;

    __half *hA, *hB;
    cudaGetSymbolAddress((void**)&hA, g_hA);
    cudaGetSymbolAddress((void**)&hB, g_hB);

    // CSR build (4 launches)
    zero_init_kernel<<<(NV + 255) / 256, 256>>>(b_out, y);
    hist_kernel<<<(EE + 255) / 256, 256>>>(dst);
    scan_kernel<<<1, SB_T>>>();
    fill_kernel<<<(EE + 255) / 256, 256>>>(src, dst);

    const int agg_blocks = (NV * 32 + 255) / 256;             // 8 warps/block

    // layer 0 conv (fp32 x -> fp16 h)
    conv_kernel<<<NV / 2, 256>>>(x_in, conv_w + 0 * KK, conv_b + 0, hA);
    // agg0 + conv1 fused
    agg_conv_kernel<<<agg_blocks, 256>>>((const uint4*)hA, (uint4*)hB,
                                         conv_w + 1 * KK, conv_b + 1);
    // agg1 + conv2 fused
    agg_conv_kernel<<<agg_blocks, 256>>>((const uint4*)hB, (uint4*)hA,
                                         conv_w + 2 * KK, conv_b + 2);
    // final agg -> g_xh (fp16)
    agg_final_kernel<<<agg_blocks, 256>>>((const uint4*)hA);

    // projection
    out_kernel2<<<(NV + OCHUNK - 1) / OCHUNK, 256>>>(W_out, y);
}